// round 9
// baseline (speedup 1.0000x reference)
#include <cuda_runtime.h>

#define EMBED   1024
#define EPB     8
#define NB      64
#define KTOP    2
#define SPLIT   8
#define CAP     2048   // worst-case tokens per (bucket,slice) block

// ---------------------------------------------------------------------------
// Single fused kernel. One block per (bucket, slice).
//  - inline op_id dtype probe (64 odd-word samples, redundant per block)
//  - stage bucket's 8 keys to smem, normalize in-block (warp w = row w)
//  - scan a CONTIGUOUS token slice, collect matches (uint16 list)
//  - 4 tokens per warp pass; butterfly all-reduce; softmax+top2 on lanes 0-3
// Output f32: out[0:ntok*K]=gid (exact small ints), out[ntok*K:2*ntok*K]=w.
// ---------------------------------------------------------------------------
__global__ __launch_bounds__(256) void router_kernel(
    const float* __restrict__ h,
    const void*  __restrict__ op_raw,
    const float* __restrict__ key,
    float*       __restrict__ out,
    int ntok)
{
    __shared__ float          skey[EPB * EMBED];   // 32 KB
    __shared__ unsigned short slist[CAP];          // 4 KB
    __shared__ int            scount;
    __shared__ int            any_nz;

    const int bucket = blockIdx.x / SPLIT;
    const int slice  = blockIdx.x % SPLIT;
    const int tid    = threadIdx.x;
    const int wid    = tid >> 5;
    const int lane   = tid & 31;

    if (tid == 0) { scount = 0; any_nz = 0; }
    __syncthreads();

    // --- dtype probe: if op_id were int64 LE, odd 32-bit words are all zero.
    {
        const int* op32 = (const int*)op_raw;
        if (tid < 64 && (2 * tid + 1) < ntok)      // safe under int32 reading
            if (op32[2 * tid + 1] != 0) atomicOr(&any_nz, 1);
    }

    // --- stage this bucket's raw keys (float4)
    const float4* kg = (const float4*)(key + (size_t)bucket * EPB * EMBED);
    float4*       ks = (float4*)skey;
    #pragma unroll
    for (int r = 0; r < 8; r++) ks[tid + 256 * r] = kg[tid + 256 * r];
    __syncthreads();

    const int is64 = any_nz ? 0 : 1;

    // --- scan contiguous token slice, collect matches
    {
        const int cands  = (ntok + SPLIT - 1) / SPLIT;
        const int tstart = slice * cands;
        const int tend   = (tstart + cands < ntok) ? (tstart + cands) : ntok;
        for (int t = tstart + tid; t < tend; t += 256) {
            long long v = is64 ? ((const long long*)op_raw)[t]
                               : (long long)((const int*)op_raw)[t];
            int b = (int)(v < 0 ? 0LL : (v > (NB - 1) ? (long long)(NB - 1) : v));
            if (b == bucket) {
                int p = atomicAdd(&scount, 1);
                if (p < CAP) slist[p] = (unsigned short)t;
            }
        }
    }

    // --- normalize key row `wid` in smem (8 warps = 8 rows)
    {
        float4 v[8];
        float  ss = 0.f;
        #pragma unroll
        for (int k = 0; k < 8; k++) {
            v[k] = ks[wid * 256 + k * 32 + lane];
            ss += v[k].x * v[k].x + v[k].y * v[k].y + v[k].z * v[k].z + v[k].w * v[k].w;
        }
        #pragma unroll
        for (int o = 16; o; o >>= 1) ss += __shfl_xor_sync(0xffffffffu, ss, o);
        float rn = 1.0f / fmaxf(sqrtf(ss), 1e-12f);
        #pragma unroll
        for (int k = 0; k < 8; k++) {
            v[k].x *= rn; v[k].y *= rn; v[k].z *= rn; v[k].w *= rn;
            ks[wid * 256 + k * 32 + lane] = v[k];
        }
    }
    __syncthreads();

    const int count = scount < CAP ? scount : CAP;
    const int btk   = ntok * KTOP;          // float offset of the 'w' block
    const float4* h4p = (const float4*)h;

    for (int base = wid * 4; base < count; base += 8 * 4) {
        int  t[4];
        bool val[4];
        #pragma unroll
        for (int i = 0; i < 4; i++) {
            val[i] = (base + i) < count;
            t[i]   = (int)slist[val[i] ? (base + i) : base];
        }

        float acc[4][EPB];
        float hh[4];
        #pragma unroll
        for (int i = 0; i < 4; i++) {
            hh[i] = 0.f;
            #pragma unroll
            for (int e = 0; e < EPB; e++) acc[i][e] = 0.f;
        }

        #pragma unroll
        for (int c = 0; c < 8; c++) {
            float4 hv[4];
            #pragma unroll
            for (int i = 0; i < 4; i++)
                hv[i] = h4p[(size_t)t[i] * (EMBED / 4) + c * 32 + lane];
            #pragma unroll
            for (int i = 0; i < 4; i++)
                hh[i] += hv[i].x * hv[i].x + hv[i].y * hv[i].y
                       + hv[i].z * hv[i].z + hv[i].w * hv[i].w;
            #pragma unroll
            for (int e = 0; e < EPB; e++) {
                float4 k4 = ks[e * (EMBED / 4) + c * 32 + lane];
                #pragma unroll
                for (int i = 0; i < 4; i++)
                    acc[i][e] += hv[i].x * k4.x + hv[i].y * k4.y
                               + hv[i].z * k4.z + hv[i].w * k4.w;
            }
        }

        // Butterfly all-reduce: every lane ends with full sums
        #pragma unroll
        for (int i = 0; i < 4; i++) {
            #pragma unroll
            for (int o = 16; o; o >>= 1) hh[i] += __shfl_xor_sync(0xffffffffu, hh[i], o);
            #pragma unroll
            for (int e = 0; e < EPB; e++) {
                #pragma unroll
                for (int o = 16; o; o >>= 1)
                    acc[i][e] += __shfl_xor_sync(0xffffffffu, acc[i][e], o);
            }
        }

        if (lane < 4 && val[lane]) {
            const int i  = lane;
            const int tt = t[i];
            float rh = 1.0f / fmaxf(sqrtf(hh[i]), 1e-12f);

            float p[EPB];
            float m = -1e30f;
            #pragma unroll
            for (int e = 0; e < EPB; e++) {
                p[e] = acc[i][e] * rh;      // TAU = 1.0
                m = fmaxf(m, p[e]);
            }
            float Z = 0.f;
            #pragma unroll
            for (int e = 0; e < EPB; e++) { p[e] = expf(p[e] - m); Z += p[e]; }

            // top-1 then top-2 (strict > => lowest index wins ties, like top_k)
            int   i1 = 0; float v1 = p[0];
            #pragma unroll
            for (int e = 1; e < EPB; e++) if (p[e] > v1) { v1 = p[e]; i1 = e; }
            int   i2 = -1; float v2 = -1.f;
            #pragma unroll
            for (int e = 0; e < EPB; e++)
                if (e != i1 && p[e] > v2) { v2 = p[e]; i2 = e; }

            v1 /= Z; v2 /= Z;
            float ws = v1 + v2 + 1e-9f;

            out[tt * 2 + 0]       = (float)(bucket * EPB + i1);
            out[tt * 2 + 1]       = (float)(bucket * EPB + i2);
            out[btk + tt * 2 + 0] = v1 / ws;
            out[btk + tt * 2 + 1] = v2 / ws;
        }
    }
}

// ---------------------------------------------------------------------------
extern "C" void kernel_launch(void* const* d_in, const int* in_sizes, int n_in,
                              void* d_out, int out_size)
{
    const float* h   = (const float*)d_in[0];
    const void*  op  = d_in[1];
    const float* key = (const float*)d_in[2];
    float*       out = (float*)d_out;
    int ntok = in_sizes[1];

    router_kernel<<<NB * SPLIT, 256>>>(h, op, key, out, ntok);
}